// round 3
// baseline (speedup 1.0000x reference)
#include <cuda_runtime.h>
#include <cstdint>
#include <cstddef>

#define Bsz 4096
#define Tsz 60
#define Dsz 200
#define Hsz 64
#define G4  256
#define BT  (Bsz*Tsz)       // 245760
#define M2  (2*BT)          // 491520
#define FCK (2*Tsz*Hsz)     // 7680
#define KSPLIT 4
#define KCHUNK (FCK/KSPLIT) // 1920

// ---------------- scratch (device globals: allocation-free) ----------------
__device__ float g_XG[(size_t)M2 * G4];                  // layer-0 gate pre-activations
__device__ float g_FEAT[(size_t)Bsz * FCK];              // relu(concat) layout
__device__ float g_FC1P[(size_t)KSPLIT * Bsz * 128];     // split-K partials
__device__ float g_FC1R[(size_t)Bsz * 128];
__device__ float g_PART[240];
__device__ float g_INV[1];

// ---------------- activations: single-MUFU tanh ----------------
__device__ __forceinline__ float tanh_fast(float x) {
    float y;
    asm("tanh.approx.f32 %0, %1;" : "=f"(y) : "f"(x));
    return y;
}
__device__ __forceinline__ float sig_fast(float x) {
    return fmaf(tanh_fast(0.5f * x), 0.5f, 0.5f);
}

// ---------------- fp32 GEMM: C[M,N] = A[M,K] * W[N,K]^T (+bias) ----------------
// BM=64, 256 threads, TM=8 x TN micro-tile, double-buffered smem.
// Warp shaped 4(ty) x 8(tx): Bs LDS.128 = 8 distinct addrs (1 crossbar cycle),
// As LDS.128 = 4 distinct addrs -> smem-bound removed, fma-bound.
template<int BN, int TN, int NB, bool RELU>
__global__ void __launch_bounds__(256) gemm_nt(
    const float* __restrict__ A, int lda, int Kloop,
    const float* __restrict__ W, int ldw,
    const float* __restrict__ b0, const float* __restrict__ b1,
    float* __restrict__ C, int ldc, size_t csplit)
{
    constexpr int BM = 64, BK = 8, TM = 8;
    constexpr int BL = (BN * BK) / 256;         // 8 (BN=256) or 4 (BN=128)
    __shared__ float As[2][BK][BM];
    __shared__ float Bs[2][BK][BN];

    const int tid  = threadIdx.x;
    const int lane = tid & 31;
    const int warp = tid >> 5;
    const int tx   = (warp & 3) * 8 + (lane & 7);   // 0..31
    const int ty   = (warp >> 2) * 4 + (lane >> 3); // 0..7
    const int row0 = blockIdx.x * BM;
    const int col0 = blockIdx.y * BN;
    const int koff = blockIdx.z * Kloop;

    const float* Ab = A + (size_t)row0 * lda + koff;
    const float* Wb = W + (size_t)col0 * ldw + koff;
    float* Cb = C + (size_t)blockIdx.z * csplit;

    const int ar = (2 * tid) >> 3;              // 0..63
    const int ak = (2 * tid) & 7;               // even
    const int bn = tid % BN;
    const int bk0 = (tid / BN) * BL;

    float acc[TM][TN];
#pragma unroll
    for (int i = 0; i < TM; i++)
#pragma unroll
        for (int j = 0; j < TN; j++) acc[i][j] = 0.f;

    float2 av = *reinterpret_cast<const float2*>(Ab + (size_t)ar * lda + ak);
    float bt[BL];
#pragma unroll
    for (int i = 0; i < BL; i += 4) {
        float4 v = *reinterpret_cast<const float4*>(Wb + (size_t)bn * ldw + bk0 + i);
        bt[i] = v.x; bt[i + 1] = v.y; bt[i + 2] = v.z; bt[i + 3] = v.w;
    }
    As[0][ak][ar] = av.x;
    As[0][ak + 1][ar] = av.y;
#pragma unroll
    for (int i = 0; i < BL; i++) Bs[0][bk0 + i][bn] = bt[i];
    __syncthreads();

    int buf = 0;
    for (int k0 = 0;; k0 += BK) {
        const bool more = (k0 + BK) < Kloop;
        if (more) {
            av = *reinterpret_cast<const float2*>(Ab + (size_t)ar * lda + k0 + BK + ak);
#pragma unroll
            for (int i = 0; i < BL; i += 4) {
                float4 v = *reinterpret_cast<const float4*>(
                    Wb + (size_t)bn * ldw + k0 + BK + bk0 + i);
                bt[i] = v.x; bt[i + 1] = v.y; bt[i + 2] = v.z; bt[i + 3] = v.w;
            }
        }

#pragma unroll
        for (int kk = 0; kk < BK; kk++) {
            float a[TM], bb[TN];
            float4 a0 = *reinterpret_cast<const float4*>(&As[buf][kk][ty * TM]);
            float4 a1 = *reinterpret_cast<const float4*>(&As[buf][kk][ty * TM + 4]);
            a[0] = a0.x; a[1] = a0.y; a[2] = a0.z; a[3] = a0.w;
            a[4] = a1.x; a[5] = a1.y; a[6] = a1.z; a[7] = a1.w;
#pragma unroll
            for (int j = 0; j < TN; j += 4) {
                float4 b4 = *reinterpret_cast<const float4*>(&Bs[buf][kk][tx * TN + j]);
                bb[j] = b4.x; bb[j + 1] = b4.y; bb[j + 2] = b4.z; bb[j + 3] = b4.w;
            }
#pragma unroll
            for (int i = 0; i < TM; i++)
#pragma unroll
                for (int j = 0; j < TN; j++)
                    acc[i][j] = fmaf(a[i], bb[j], acc[i][j]);
        }

        if (!more) break;
        As[buf ^ 1][ak][ar] = av.x;
        As[buf ^ 1][ak + 1][ar] = av.y;
#pragma unroll
        for (int i = 0; i < BL; i++) Bs[buf ^ 1][bk0 + i][bn] = bt[i];
        __syncthreads();
        buf ^= 1;
    }

    float bv[TN];
#pragma unroll
    for (int j = 0; j < TN; j++) {
        bv[j] = 0.f;
        if (NB >= 1) bv[j] += b0[col0 + tx * TN + j];
        if (NB >= 2) bv[j] += b1[col0 + tx * TN + j];
    }
#pragma unroll
    for (int i = 0; i < TM; i++) {
        float* Cr = Cb + (size_t)(row0 + ty * TM + i) * ldc + col0 + tx * TN;
#pragma unroll
        for (int j = 0; j < TN; j += 4) {
            float4 v;
            v.x = acc[i][j + 0] + bv[j + 0];
            v.y = acc[i][j + 1] + bv[j + 1];
            v.z = acc[i][j + 2] + bv[j + 2];
            v.w = acc[i][j + 3] + bv[j + 3];
            if (RELU) {
                v.x = fmaxf(v.x, 0.f); v.y = fmaxf(v.y, 0.f);
                v.z = fmaxf(v.z, 0.f); v.w = fmaxf(v.w, 0.f);
            }
            *reinterpret_cast<float4*>(Cr + j) = v;
        }
    }
}

// ---------------- fused 2-layer LSTM recurrence ----------------
// 4 batch rows per CTA, 512 threads (16 warps, 1 CTA/SM).
// Thread (g = tid&255, kh = tid>>8) owns gate column g for the k-half
// [kh*32, kh*32+32) of all three weight matrices (96 regs).
// One-step skew: phase A computes layer-0 gates(t) and layer-1 gates(t-1)
// together, sharing the h0(t-1) shared-memory loads. Phase B runs both
// activations (threads 0..255) and writes relu(h1) directly to FEAT.
__global__ void __launch_bounds__(512, 1) lstm_fused(
    const float* __restrict__ XG,     // [8192*T, 256] layer-0 preacts (biases folded)
    const float* __restrict__ Whh0,   // [256, 64]
    const float* __restrict__ Wih1,   // [256, 64]
    const float* __restrict__ Whh1,   // [256, 64]
    const float* __restrict__ bih1, const float* __restrict__ bhh1,
    float* __restrict__ FEAT)
{
    __shared__ float4 sh_h0[4][16];          // h0 [4 rows][64]
    __shared__ float4 sh_h1[4][16];          // h1 [4 rows][64]
    __shared__ float  sg0[2][4][G4];         // layer-0 gate partials per k-half
    __shared__ float  sg1[2][4][G4];         // layer-1 gate partials per k-half
    float* h0f = reinterpret_cast<float*>(sh_h0);
    float* h1f = reinterpret_cast<float*>(sh_h1);

    const int tid = threadIdx.x;
    const int g   = tid & 255;
    const int kh  = tid >> 8;                // 0 or 1
    const int kb  = kh * 8;                  // float4 offset of this k-half

    // weight half-rows in registers: 3 x 32 = 96 regs
    float w0[32], wi[32], w1[32];
    {
        const float4* p0 = reinterpret_cast<const float4*>(Whh0 + (size_t)g * Hsz) + kb;
        const float4* pi = reinterpret_cast<const float4*>(Wih1 + (size_t)g * Hsz) + kb;
        const float4* p1 = reinterpret_cast<const float4*>(Whh1 + (size_t)g * Hsz) + kb;
#pragma unroll
        for (int i = 0; i < 8; i++) {
            float4 v = p0[i];
            w0[4*i] = v.x; w0[4*i+1] = v.y; w0[4*i+2] = v.z; w0[4*i+3] = v.w;
        }
#pragma unroll
        for (int i = 0; i < 8; i++) {
            float4 v = pi[i];
            wi[4*i] = v.x; wi[4*i+1] = v.y; wi[4*i+2] = v.z; wi[4*i+3] = v.w;
        }
#pragma unroll
        for (int i = 0; i < 8; i++) {
            float4 v = p1[i];
            w1[4*i] = v.x; w1[4*i+1] = v.y; w1[4*i+2] = v.z; w1[4*i+3] = v.w;
        }
    }
    const float b1g = (kh == 1) ? (bih1[g] + bhh1[g]) : 0.f;

    const int row0 = blockIdx.x * 4;
    const float* xgb = XG + (size_t)row0 * Tsz * G4 + g;

    const int ar = tid >> 6;                 // valid for tid<256: 0..3
    const int aj = tid & 63;
    float c0 = 0.f, c1 = 0.f;

    if (tid < 256) { h0f[tid] = 0.f; h1f[tid] = 0.f; }
    __syncthreads();

    float xc[4] = {0.f, 0.f, 0.f, 0.f};
    if (kh == 0) {
#pragma unroll
        for (int rr = 0; rr < 4; rr++)
            xc[rr] = xgb[(size_t)rr * Tsz * G4];
    }

    for (int m = 0; m <= Tsz; m++) {
        const bool L0 = (m < Tsz);
        const bool L1 = (m >= 1);

        float xn[4];
        if (kh == 0 && m + 1 < Tsz) {
#pragma unroll
            for (int rr = 0; rr < 4; rr++)
                xn[rr] = xgb[(size_t)rr * Tsz * G4 + (size_t)(m + 1) * G4];
        }

        // ---- phase A: gates ----
#pragma unroll
        for (int rr = 0; rr < 4; rr++) {
            float a0 = xc[rr];               // layer-0: xg (kh==0) else 0
            float a1 = b1g;                  // layer-1: bias (kh==1) else 0
            const float4* hp0 = sh_h0[rr] + kb;
            const float4* hp1 = sh_h1[rr] + kb;
#pragma unroll
            for (int k = 0; k < 8; k++) {
                float4 hv = hp0[k];
                a0 = fmaf(hv.x, w0[4*k+0], a0);
                a0 = fmaf(hv.y, w0[4*k+1], a0);
                a0 = fmaf(hv.z, w0[4*k+2], a0);
                a0 = fmaf(hv.w, w0[4*k+3], a0);
                a1 = fmaf(hv.x, wi[4*k+0], a1);
                a1 = fmaf(hv.y, wi[4*k+1], a1);
                a1 = fmaf(hv.z, wi[4*k+2], a1);
                a1 = fmaf(hv.w, wi[4*k+3], a1);
            }
#pragma unroll
            for (int k = 0; k < 8; k++) {
                float4 hv = hp1[k];
                a1 = fmaf(hv.x, w1[4*k+0], a1);
                a1 = fmaf(hv.y, w1[4*k+1], a1);
                a1 = fmaf(hv.z, w1[4*k+2], a1);
                a1 = fmaf(hv.w, w1[4*k+3], a1);
            }
            if (L0) sg0[kh][rr][g] = a0;
            if (L1) sg1[kh][rr][g] = a1;
        }
        __syncthreads();

        // ---- phase B: activations (threads 0..255) ----
        if (tid < 256) {
            if (L0) {
                float iv = sg0[0][ar][aj]       + sg0[1][ar][aj];
                float fv = sg0[0][ar][aj + 64]  + sg0[1][ar][aj + 64];
                float gv = sg0[0][ar][aj + 128] + sg0[1][ar][aj + 128];
                float ov = sg0[0][ar][aj + 192] + sg0[1][ar][aj + 192];
                c0 = sig_fast(fv) * c0 + sig_fast(iv) * tanh_fast(gv);
                h0f[ar * 64 + aj] = sig_fast(ov) * tanh_fast(c0);
            }
            if (L1) {
                float iv = sg1[0][ar][aj]       + sg1[1][ar][aj];
                float fv = sg1[0][ar][aj + 64]  + sg1[1][ar][aj + 64];
                float gv = sg1[0][ar][aj + 128] + sg1[1][ar][aj + 128];
                float ov = sg1[0][ar][aj + 192] + sg1[1][ar][aj + 192];
                c1 = sig_fast(fv) * c1 + sig_fast(iv) * tanh_fast(gv);
                float h = sig_fast(ov) * tanh_fast(c1);
                h1f[ar * 64 + aj] = h;
                int row = row0 + ar;
                int inp = row >> 12, b = row & (Bsz - 1);
                FEAT[(size_t)b * FCK + (size_t)inp * (Tsz * Hsz)
                     + (size_t)(m - 1) * Hsz + aj] = fmaxf(h, 0.f);
            }
        }
        __syncthreads();

        if (kh == 0 && m + 1 < Tsz) {
#pragma unroll
            for (int rr = 0; rr < 4; rr++) xc[rr] = xn[rr];
        }
    }
}

// ---------------- FC1 split-K reduction (+bias, +relu) ----------------
__global__ void __launch_bounds__(256) fc1_reduce(
    const float* __restrict__ part, const float* __restrict__ bias,
    float* __restrict__ outp)
{
    const size_t S = (size_t)Bsz * 128;
    size_t i = (size_t)blockIdx.x * 256 + threadIdx.x;
    int n = (int)(i & 127);
    float s = bias[n] + part[i] + part[i + S] + part[i + 2 * S] + part[i + 3 * S];
    outp[i] = fmaxf(s, 0.f);
}

// ---------------- FC2 + partial sum-of-squares ----------------
__global__ void __launch_bounds__(256) fc2_norm(
    const float* __restrict__ fc1, const float* __restrict__ w,
    const float* __restrict__ bias, float* __restrict__ out,
    float* __restrict__ partial)
{
    __shared__ float sw[15 * 132];
    __shared__ float red[256];
    const int tid = threadIdx.x;
    for (int i = tid; i < 15 * 128; i += 256) {
        int n = i >> 7, k = i & 127;
        sw[n * 132 + k] = w[i];
    }
    __syncthreads();

    int idx = blockIdx.x * 256 + tid;
    int b = idx / 15, n = idx - b * 15;
    const float4* fr = reinterpret_cast<const float4*>(fc1 + (size_t)b * 128);
    const float4* wn = reinterpret_cast<const float4*>(sw + n * 132);
    float acc = bias[n];
#pragma unroll
    for (int k = 0; k < 32; k++) {
        float4 f4 = fr[k];
        float4 w4 = wn[k];
        acc = fmaf(f4.x, w4.x, acc);
        acc = fmaf(f4.y, w4.y, acc);
        acc = fmaf(f4.z, w4.z, acc);
        acc = fmaf(f4.w, w4.w, acc);
    }
    out[idx] = acc;
    red[tid] = acc * acc;
    __syncthreads();
#pragma unroll
    for (int s = 128; s > 0; s >>= 1) {
        if (tid < s) red[tid] += red[tid + s];
        __syncthreads();
    }
    if (tid == 0) partial[blockIdx.x] = red[0];
}

__global__ void reduce_norm(const float* __restrict__ partial, float* __restrict__ inv)
{
    __shared__ float red[256];
    float s = 0.f;
    for (int i = threadIdx.x; i < 240; i += 256) s += partial[i];
    red[threadIdx.x] = s;
    __syncthreads();
#pragma unroll
    for (int st = 128; st > 0; st >>= 1) {
        if (threadIdx.x < st) red[threadIdx.x] += red[threadIdx.x + st];
        __syncthreads();
    }
    if (threadIdx.x == 0) inv[0] = 1.0f / sqrtf(red[0]);
}

__global__ void scale_out(float* __restrict__ out, const float* __restrict__ inv)
{
    int i = blockIdx.x * 256 + threadIdx.x;
    out[i] *= inv[0];
}

// ---------------- launch ----------------
extern "C" void kernel_launch(void* const* d_in, const int* in_sizes, int n_in,
                              void* d_out, int out_size)
{
    const float* x1      = (const float*)d_in[0];
    const float* x2      = (const float*)d_in[1];
    const float* W_ih_l0 = (const float*)d_in[2];
    const float* W_hh_l0 = (const float*)d_in[3];
    const float* b_ih_l0 = (const float*)d_in[4];
    const float* b_hh_l0 = (const float*)d_in[5];
    const float* W_ih_l1 = (const float*)d_in[6];
    const float* W_hh_l1 = (const float*)d_in[7];
    const float* b_ih_l1 = (const float*)d_in[8];
    const float* b_hh_l1 = (const float*)d_in[9];
    const float* fc1_w   = (const float*)d_in[10];
    const float* fc1_b   = (const float*)d_in[11];
    const float* fc2_w   = (const float*)d_in[12];
    const float* fc2_b   = (const float*)d_in[13];
    float* out = (float*)d_out;

    float *XG, *FEAT, *FC1P, *FC1R, *PART, *INV;
    cudaGetSymbolAddress((void**)&XG,   g_XG);
    cudaGetSymbolAddress((void**)&FEAT, g_FEAT);
    cudaGetSymbolAddress((void**)&FC1P, g_FC1P);
    cudaGetSymbolAddress((void**)&FC1R, g_FC1R);
    cudaGetSymbolAddress((void**)&PART, g_PART);
    cudaGetSymbolAddress((void**)&INV,  g_INV);

    // layer-0 input projection (both sequences), biases folded in
    gemm_nt<256, 8, 2, false><<<dim3(BT / 64, 1, 1), 256>>>(
        x1, Dsz, Dsz, W_ih_l0, Dsz, b_ih_l0, b_hh_l0, XG, G4, 0);
    gemm_nt<256, 8, 2, false><<<dim3(BT / 64, 1, 1), 256>>>(
        x2, Dsz, Dsz, W_ih_l0, Dsz, b_ih_l0, b_hh_l0, XG + (size_t)BT * G4, G4, 0);

    // fused 2-layer recurrence -> relu(FEAT) in concat layout
    lstm_fused<<<2048, 512>>>(XG, W_hh_l0, W_ih_l1, W_hh_l1, b_ih_l1, b_hh_l1, FEAT);

    // FC1: split-K x4, deterministic partial buffers, then reduce+bias+relu
    gemm_nt<128, 4, 0, false><<<dim3(Bsz / 64, 1, KSPLIT), 256>>>(
        FEAT, FCK, KCHUNK, fc1_w, FCK, nullptr, nullptr,
        FC1P, 128, (size_t)Bsz * 128);
    fc1_reduce<<<(Bsz * 128) / 256, 256>>>(FC1P, fc1_b, FC1R);

    // FC2 + deterministic norm + scale
    fc2_norm<<<240, 256>>>(FC1R, fc2_w, fc2_b, out, PART);
    reduce_norm<<<1, 256>>>(PART, INV);
    scale_out<<<240, 256>>>(out, INV);
}